// round 2
// baseline (speedup 1.0000x reference)
#include <cuda_runtime.h>
#include <math.h>
#include <stdint.h>

// Problem constants
#define NB   2
#define NT   2048
#define ND   512
#define NH   8
#define NHD  64
#define NQKV 1536
#define MAXROWS (NB*NT)   // 4096

// ---------------- scratch (device globals; no allocations allowed) ----------
__device__ float d_qkv   [ (size_t)MAXROWS*NQKV ];          // 25.2 MB
__device__ float d_S     [ (size_t)NB*NH*NT*NT ];           // 268 MB (scores/attn)
__device__ float d_AO    [ (size_t)MAXROWS*ND ];            // attn@v concat-head
__device__ float d_stage [ (size_t)MAXROWS*ND ];            // MHA output per stage
__device__ float d_merged[ (size_t)MAXROWS*ND ];            // merge result

__device__ int g_ids1[NT];
__device__ int g_ids2[NT];
__device__ int g_start1[NT+2];
__device__ int g_start2[NT+2];
__device__ int g_m1, g_m2, g_ntok;
__device__ int g_tokmap[NT];
__device__ int g_tokg[NT];
__device__ long long g_off[3];   // [0]=char_w off, [1]=block_w off, [2]=glob_w off

__device__ __forceinline__ int seqlen(int stage) {
    return stage == 0 ? NT : (stage == 1 ? g_m1 : g_m2);
}

// ---------------- setup: ids / starts / token map / offsets -----------------
__global__ void setup_kernel(const float* __restrict__ mw, const float* __restrict__ mb,
                             const float* __restrict__ gw, const float* __restrict__ gb) {
    if (threadIdx.x != 0 || blockIdx.x != 0) return;

    // c1 = merge_w.sum() + merge_b[0]  (sum in high precision, round to f32)
    double s = 0.0;
    for (int i = 0; i < ND; i++) s += (double)mw[i];
    float c1 = (float)s + mb[0];
    s = 0.0;
    for (int i = 0; i < ND; i++) s += (double)gw[i];
    float c2 = (float)s + gb[0];

    // ids1 = _block_ids(NT, c1): fp32 sequential cumsum, frac wrap detection.
    float cum = 0.f, last = 0.f;
    for (int i = 0; i < NT; i++) { cum += c1; last = cum - floorf(cum); }
    cum = 0.f; float prev = last; int id = 0;
    for (int i = 0; i < NT; i++) {
        cum += c1;
        float fr = cum - floorf(cum);
        if (fr < prev) id++;
        g_ids1[i] = id;
        prev = fr;
    }
    int m1 = id;
    g_m1 = m1;
    {
        int prevId = 0;
        for (int i = 0; i < NT; i++) {
            int v = g_ids1[i];
            if (v > prevId) { for (int j = prevId + 1; j <= v; j++) g_start1[j] = i; prevId = v; }
        }
        g_start1[m1 + 1] = NT;
    }

    // ids2 = _block_ids(m1, c2)
    cum = 0.f; last = 0.f;
    for (int i = 0; i < m1; i++) { cum += c2; last = cum - floorf(cum); }
    cum = 0.f; prev = last; id = 0;
    for (int i = 0; i < m1; i++) {
        cum += c2;
        float fr = cum - floorf(cum);
        if (fr < prev) id++;
        g_ids2[i] = id;
        prev = fr;
    }
    int m2 = id;
    g_m2 = m2;
    {
        int prevId = 0;
        for (int i = 0; i < m1; i++) {
            int v = g_ids2[i];
            if (v > prevId) { for (int j = prevId + 1; j <= v; j++) g_start2[j] = i; prevId = v; }
        }
        g_start2[m2 + 1] = m1;
    }

    // token_g + compaction
    int n = 0;
    for (int t = 0; t < NT; t++) {
        int i1 = g_ids1[t];
        int tg = (i1 >= 1) ? g_ids2[i1 - 1] : 0;
        g_tokg[t] = tg;
        if (tg >= 1) g_tokmap[n++] = t;
    }
    g_ntok = n;

    long long offcw = (long long)NB * n * ND;
    g_off[0] = offcw;
    g_off[1] = offcw + (long long)NB * NT * NT;
    g_off[2] = g_off[1] + (long long)NB * m1 * m1;
}

// ---------------- generic NT GEMM: C[M,N] = A[M,K] * W[N,K]^T + bias --------
// A selected by Asel: 0 = Aext (input x), 1 = d_merged, 2 = d_AO
// C selected by Csel: 0 = d_qkv, 1 = d_stage
__global__ __launch_bounds__(256)
void gemm_nt(const float* __restrict__ Aext, int Asel,
             const float* __restrict__ W, const float* __restrict__ bias,
             int Csel, int N, int K, int stage) {
    int M = NB * seqlen(stage);
    int m0 = blockIdx.y * 64, n0 = blockIdx.x * 64;
    if (m0 >= M) return;

    const float* A = (Asel == 0) ? Aext : (Asel == 1 ? d_merged : d_AO);
    float* C = (Csel == 0) ? d_qkv : d_stage;

    __shared__ float As[64][17];
    __shared__ float Bs[64][17];
    int tx = threadIdx.x, ty = threadIdx.y;
    int tid = ty * 16 + tx;
    float acc[4][4] = {};

    for (int k0 = 0; k0 < K; k0 += 16) {
        #pragma unroll
        for (int i = 0; i < 4; i++) {
            int idx = tid + i * 256;
            int r = idx >> 4, c = idx & 15;
            int gr = m0 + r;
            As[r][c] = (gr < M) ? A[(size_t)gr * K + (k0 + c)] : 0.f;
            int wr = n0 + r;
            Bs[r][c] = (wr < N) ? W[(size_t)wr * K + (k0 + c)] : 0.f;
        }
        __syncthreads();
        #pragma unroll
        for (int kk = 0; kk < 16; kk++) {
            float a[4], b[4];
            #pragma unroll
            for (int i = 0; i < 4; i++) a[i] = As[ty * 4 + i][kk];
            #pragma unroll
            for (int j = 0; j < 4; j++) b[j] = Bs[tx * 4 + j][kk];
            #pragma unroll
            for (int i = 0; i < 4; i++)
                #pragma unroll
                for (int j = 0; j < 4; j++) acc[i][j] += a[i] * b[j];
        }
        __syncthreads();
    }
    #pragma unroll
    for (int i = 0; i < 4; i++) {
        int r = m0 + ty * 4 + i;
        if (r >= M) continue;
        #pragma unroll
        for (int j = 0; j < 4; j++) {
            int c = n0 + tx * 4 + j;
            if (c < N) C[(size_t)r * N + c] = acc[i][j] + (bias ? bias[c] : 0.f);
        }
    }
}

// ---------------- batched scores: S[bh,q,k] = (Q . K)/8 ---------------------
__global__ __launch_bounds__(256)
void scores_kernel(int stage) {
    int L = seqlen(stage);
    int m0 = blockIdx.y * 64, n0 = blockIdx.x * 64;
    if (m0 >= L || n0 >= L) return;
    int bh = blockIdx.z;
    int b = bh / NH, h = bh % NH;

    const float* Qb = d_qkv + (size_t)b * L * NQKV + h * NHD;
    const float* Kb = Qb + ND;
    float* Cb = d_S + (size_t)bh * NT * NT;

    __shared__ float As[64][17];
    __shared__ float Bs[64][17];
    int tx = threadIdx.x, ty = threadIdx.y;
    int tid = ty * 16 + tx;
    float acc[4][4] = {};

    for (int k0 = 0; k0 < NHD; k0 += 16) {
        #pragma unroll
        for (int i = 0; i < 4; i++) {
            int idx = tid + i * 256;
            int r = idx >> 4, c = idx & 15;
            As[r][c] = (m0 + r < L) ? Qb[(size_t)(m0 + r) * NQKV + (k0 + c)] : 0.f;
            Bs[r][c] = (n0 + r < L) ? Kb[(size_t)(n0 + r) * NQKV + (k0 + c)] : 0.f;
        }
        __syncthreads();
        #pragma unroll
        for (int kk = 0; kk < 16; kk++) {
            float a[4], bb[4];
            #pragma unroll
            for (int i = 0; i < 4; i++) a[i] = As[ty * 4 + i][kk];
            #pragma unroll
            for (int j = 0; j < 4; j++) bb[j] = Bs[tx * 4 + j][kk];
            #pragma unroll
            for (int i = 0; i < 4; i++)
                #pragma unroll
                for (int j = 0; j < 4; j++) acc[i][j] += a[i] * bb[j];
        }
        __syncthreads();
    }
    #pragma unroll
    for (int i = 0; i < 4; i++) {
        int r = m0 + ty * 4 + i;
        if (r >= L) continue;
        #pragma unroll
        for (int j = 0; j < 4; j++) {
            int c = n0 + tx * 4 + j;
            if (c < L) Cb[(size_t)r * L + c] = 0.125f * acc[i][j];
        }
    }
}

// ---------------- row softmax in-place on d_S -------------------------------
__global__ __launch_bounds__(256)
void softmax_kernel(int stage) {
    int L = seqlen(stage);
    int q = blockIdx.x;
    if (q >= L) return;
    int bh = blockIdx.y;
    float* row = d_S + (size_t)bh * NT * NT + (size_t)q * L;

    __shared__ float red[256];
    int t = threadIdx.x;
    float v[8];
    int cnt = 0;
    float mx = -INFINITY;
    for (int k = t; k < L; k += 256) { float x = row[k]; v[cnt++] = x; mx = fmaxf(mx, x); }
    red[t] = mx; __syncthreads();
    for (int s2 = 128; s2 > 0; s2 >>= 1) { if (t < s2) red[t] = fmaxf(red[t], red[t + s2]); __syncthreads(); }
    mx = red[0]; __syncthreads();

    float sm = 0.f;
    for (int i = 0; i < cnt; i++) { float e = expf(v[i] - mx); v[i] = e; sm += e; }
    red[t] = sm; __syncthreads();
    for (int s2 = 128; s2 > 0; s2 >>= 1) { if (t < s2) red[t] += red[t + s2]; __syncthreads(); }
    float denom = red[0];

    cnt = 0;
    for (int k = t; k < L; k += 256) row[k] = v[cnt++] / denom;
}

// ---------------- head-mean of attn -> d_out (char_w / block_w / glob_w) ----
__global__ __launch_bounds__(256)
void wmean_kernel(int stage, float* __restrict__ out) {
    int L = seqlen(stage);
    int q = blockIdx.x;
    if (q >= L) return;
    int b = blockIdx.y;
    float* dst = out + g_off[stage] + ((size_t)b * L + q) * L;
    for (int k = threadIdx.x; k < L; k += 256) {
        float s = 0.f;
        #pragma unroll
        for (int h = 0; h < NH; h++)
            s += d_S[(size_t)(b * NH + h) * NT * NT + (size_t)q * L + k];
        dst[k] = 0.125f * s;
    }
}

// ---------------- attn @ V -> d_AO (concat-head layout [B*L, 512]) ----------
__global__ __launch_bounds__(256)
void av_kernel(int stage) {
    int L = seqlen(stage);
    int m0 = blockIdx.y * 64;
    if (m0 >= L) return;
    int bh = blockIdx.z;
    int b = bh / NH, h = bh % NH;

    const float* P = d_S + (size_t)bh * NT * NT;
    const float* V = d_qkv + (size_t)b * L * NQKV + 2 * ND + h * NHD;
    float* C = d_AO + ((size_t)b * L) * ND + h * NHD;

    __shared__ float As[64][17];   // P tile [m][k]
    __shared__ float Bs[16][65];   // V tile [k][n]
    int tx = threadIdx.x, ty = threadIdx.y;
    int tid = ty * 16 + tx;
    float acc[4][4] = {};

    for (int k0 = 0; k0 < L; k0 += 16) {
        #pragma unroll
        for (int i = 0; i < 4; i++) {
            int idx = tid + i * 256;
            int r = idx >> 4, c = idx & 15;
            As[r][c] = (m0 + r < L && k0 + c < L) ? P[(size_t)(m0 + r) * L + (k0 + c)] : 0.f;
        }
        #pragma unroll
        for (int i = 0; i < 4; i++) {
            int idx = tid + i * 256;
            int kr = idx >> 6, nc = idx & 63;
            Bs[kr][nc] = (k0 + kr < L) ? V[(size_t)(k0 + kr) * NQKV + nc] : 0.f;
        }
        __syncthreads();
        #pragma unroll
        for (int kk = 0; kk < 16; kk++) {
            float a[4], bb[4];
            #pragma unroll
            for (int i = 0; i < 4; i++) a[i] = As[ty * 4 + i][kk];
            #pragma unroll
            for (int j = 0; j < 4; j++) bb[j] = Bs[kk][tx * 4 + j];
            #pragma unroll
            for (int i = 0; i < 4; i++)
                #pragma unroll
                for (int j = 0; j < 4; j++) acc[i][j] += a[i] * bb[j];
        }
        __syncthreads();
    }
    #pragma unroll
    for (int i = 0; i < 4; i++) {
        int r = m0 + ty * 4 + i;
        if (r >= L) continue;
        #pragma unroll
        for (int j = 0; j < 4; j++) C[(size_t)r * ND + (tx * 4 + j)] = acc[i][j];
    }
}

// ---------------- segment mean merge: d_stage -> d_merged -------------------
__global__ __launch_bounds__(256)
void merge_kernel(int which) {   // 1: char->blocks (ids1), 2: blocks->glob (ids2)
    int m   = (which == 1) ? g_m1 : g_m2;
    int Tin = (which == 1) ? NT : g_m1;
    const int* start = (which == 1) ? g_start1 : g_start2;
    int j = blockIdx.x + 1;
    if (j > m) return;
    int b = blockIdx.y;
    int s0 = start[j], s1 = start[j + 1];
    float cnt = (float)(s1 - s0);
    const float* in = d_stage + ((size_t)b * Tin) * ND;
    float* outp = d_merged + ((size_t)(b * m + (j - 1))) * ND;
    for (int d = threadIdx.x; d < ND; d += 256) {
        float s = 0.f;
        for (int t = s0; t < s1; t++) s += in[(size_t)t * ND + d];
        outp[d] = s / (cnt + 1e-10f);
    }
}

// ---------------- expand glob_out to selected tokens -> d_out[0..] ----------
__global__ __launch_bounds__(256)
void expand_kernel(float* __restrict__ out) {
    int i = blockIdx.x;
    if (i >= g_ntok) return;
    int b = blockIdx.y;
    int t = g_tokmap[i];
    int gsrc = g_tokg[t] - 1;
    int m2 = g_m2;
    const float* src = d_stage + ((size_t)(b * m2 + gsrc)) * ND;
    float* dst = out + ((size_t)b * g_ntok + i) * ND;
    for (int d = threadIdx.x; d < ND; d += 256) dst[d] = src[d];
}

// ---------------- launch ----------------------------------------------------
extern "C" void kernel_launch(void* const* d_in, const int* in_sizes, int n_in,
                              void* d_out, int out_size) {
    (void)in_sizes; (void)n_in; (void)out_size;
    const float* x    = (const float*)d_in[0];
    const float* cWi  = (const float*)d_in[1];
    const float* cbi  = (const float*)d_in[2];
    const float* cWo  = (const float*)d_in[3];
    const float* cbo  = (const float*)d_in[4];
    const float* bWi  = (const float*)d_in[5];
    const float* bbi  = (const float*)d_in[6];
    const float* bWo  = (const float*)d_in[7];
    const float* bbo  = (const float*)d_in[8];
    const float* gWi  = (const float*)d_in[9];
    const float* gbi  = (const float*)d_in[10];
    const float* gWo  = (const float*)d_in[11];
    const float* gbo  = (const float*)d_in[12];
    const float* mw   = (const float*)d_in[13];
    const float* mb   = (const float*)d_in[14];
    const float* gmw  = (const float*)d_in[15];
    const float* gmb  = (const float*)d_in[16];
    float* out = (float*)d_out;

    dim3 thr(16, 16);

    setup_kernel<<<1, 1>>>(mw, mb, gmw, gmb);

    // ---- char stage (L = 2048) ----
    gemm_nt<<<dim3(NQKV / 64, MAXROWS / 64), thr>>>(x, 0, cWi, cbi, 0, NQKV, ND, 0);
    scores_kernel<<<dim3(NT / 64, NT / 64, NB * NH), thr>>>(0);
    softmax_kernel<<<dim3(NT, NB * NH), 256>>>(0);
    wmean_kernel<<<dim3(NT, NB), 256>>>(0, out);
    av_kernel<<<dim3(1, NT / 64, NB * NH), thr>>>(0);
    gemm_nt<<<dim3(ND / 64, MAXROWS / 64), thr>>>(nullptr, 2, cWo, cbo, 1, ND, ND, 0);

    // ---- merge 1 ----
    merge_kernel<<<dim3(NT, NB), 256>>>(1);

    // ---- block stage (L = m1) ----
    gemm_nt<<<dim3(NQKV / 64, MAXROWS / 64), thr>>>(nullptr, 1, bWi, bbi, 0, NQKV, ND, 1);
    scores_kernel<<<dim3(NT / 64, NT / 64, NB * NH), thr>>>(1);
    softmax_kernel<<<dim3(NT, NB * NH), 256>>>(1);
    wmean_kernel<<<dim3(NT, NB), 256>>>(1, out);
    av_kernel<<<dim3(1, NT / 64, NB * NH), thr>>>(1);
    gemm_nt<<<dim3(ND / 64, MAXROWS / 64), thr>>>(nullptr, 2, bWo, bbo, 1, ND, ND, 1);

    // ---- merge 2 ----
    merge_kernel<<<dim3(NT, NB), 256>>>(2);

    // ---- glob stage (L = m2) ----
    gemm_nt<<<dim3(NQKV / 64, MAXROWS / 64), thr>>>(nullptr, 1, gWi, gbi, 0, NQKV, ND, 2);
    scores_kernel<<<dim3(NT / 64, NT / 64, NB * NH), thr>>>(2);
    softmax_kernel<<<dim3(NT, NB * NH), 256>>>(2);
    wmean_kernel<<<dim3(NT, NB), 256>>>(2, out);
    av_kernel<<<dim3(1, NT / 64, NB * NH), thr>>>(2);
    gemm_nt<<<dim3(ND / 64, MAXROWS / 64), thr>>>(nullptr, 2, gWo, gbo, 1, ND, ND, 2);

    // ---- expand ----
    expand_kernel<<<dim3(NT, NB), 256>>>(out);
}